// round 1
// baseline (speedup 1.0000x reference)
#include <cuda_runtime.h>

// Problem constants (fixed by the dataset)
#define NB   8
#define C_   128
#define H_   96
#define W_   96
#define CO_  128
#define K2_  9
#define HW_  (H_ * W_)      // 9216
#define PT   64             // output pixels per block
#define TILES_PER_IMG (HW_ / PT)   // 144

// smem layout (floats): wsm[128*128] | vsm[128*64] | idx4[9*64*4 ints] | wt4[9*64*4]
#define SMEM_WSM_F   (C_ * CO_)          // 16384
#define SMEM_VSM_F   (C_ * PT)           // 8192
#define SMEM_META_I  (K2_ * PT * 4)      // 2304 ints
#define SMEM_BYTES   ((SMEM_WSM_F + SMEM_VSM_F) * 4 + SMEM_META_I * 4 * 2)  // 116736

// [k2][c][co] transposed weights
__device__ float g_wT[K2_ * C_ * CO_];

__global__ void transpose_weight_kernel(const float* __restrict__ w) {
    int i = blockIdx.x * blockDim.x + threadIdx.x;
    if (i >= K2_ * C_ * CO_) return;
    int co = i % CO_;
    int c  = (i / CO_) % C_;
    int k2 = i / (CO_ * C_);
    g_wT[i] = w[(co * C_ + c) * K2_ + k2];
}

__global__ __launch_bounds__(256, 1)
void deform_conv_kernel(const float* __restrict__ x,
                        const float* __restrict__ offset,
                        const float* __restrict__ mask,
                        const float* __restrict__ bias,
                        float* __restrict__ out) {
    extern __shared__ float smem[];
    float* wsm  = smem;                              // [c][co] 128x128
    float* vsm  = smem + SMEM_WSM_F;                 // [c][p]  128x64
    int*   sidx = (int*)(smem + SMEM_WSM_F + SMEM_VSM_F);   // [k2*PT][4]
    float* swt  = (float*)(sidx + SMEM_META_I);             // [k2*PT][4]

    const int tid    = threadIdx.x;
    const int tile   = blockIdx.x;                   // 0..NB*144-1
    const int n      = tile / TILES_PER_IMG;
    const int p_base = (tile % TILES_PER_IMG) * PT;

    const float* xn = x + (size_t)n * C_ * HW_;

    // -------- Phase 0: per-(k2, pixel) bilinear sample metadata --------
    for (int i = tid; i < K2_ * PT; i += 256) {
        int k2 = i / PT;
        int p  = i % PT;
        int pg = p_base + p;
        int oy = pg / W_;
        int ox = pg % W_;

        float offY = offset[((size_t)(n * (2 * K2_) + 2 * k2)     ) * HW_ + pg];
        float offX = offset[((size_t)(n * (2 * K2_) + 2 * k2 + 1)) * HW_ + pg];
        float m    = mask[((size_t)(n * K2_ + k2)) * HW_ + pg];

        int ky = k2 / 3, kx = k2 % 3;
        float py = (float)(oy - 1 + ky) + offY;
        float px = (float)(ox - 1 + kx) + offX;

        float y0f = floorf(py), x0f = floorf(px);
        float wy = py - y0f, wx = px - x0f;
        int y0 = (int)y0f, x0 = (int)x0f;
        int y1 = y0 + 1,   x1 = x0 + 1;

        bool vy0 = (y0 >= 0) & (y0 < H_);
        bool vy1 = (y1 >= 0) & (y1 < H_);
        bool vx0 = (x0 >= 0) & (x0 < W_);
        bool vx1 = (x1 >= 0) & (x1 < W_);

        int cy0 = min(max(y0, 0), H_ - 1);
        int cy1 = min(max(y1, 0), H_ - 1);
        int cx0 = min(max(x0, 0), W_ - 1);
        int cx1 = min(max(x1, 0), W_ - 1);

        float w00 = (vy0 & vx0) ? (1.f - wy) * (1.f - wx) * m : 0.f;
        float w01 = (vy0 & vx1) ? (1.f - wy) * wx * m         : 0.f;
        float w10 = (vy1 & vx0) ? wy * (1.f - wx) * m         : 0.f;
        float w11 = (vy1 & vx1) ? wy * wx * m                 : 0.f;

        int b = i * 4;
        sidx[b + 0] = cy0 * W_ + cx0;
        sidx[b + 1] = cy0 * W_ + cx1;
        sidx[b + 2] = cy1 * W_ + cx0;
        sidx[b + 3] = cy1 * W_ + cx1;
        swt[b + 0] = w00;
        swt[b + 1] = w01;
        swt[b + 2] = w10;
        swt[b + 3] = w11;
    }

    // -------- Register tile setup: 8 co x 4 p per thread --------
    const int ty  = tid >> 4;        // 0..15
    const int tx  = tid & 15;        // 0..15
    const int co0 = ty * 8;
    const int p0  = tx * 4;

    float acc[8][4];
#pragma unroll
    for (int i = 0; i < 8; i++)
#pragma unroll
        for (int j = 0; j < 4; j++) acc[i][j] = 0.f;

    // -------- Main loop over kernel taps --------
    for (int k2 = 0; k2 < K2_; k2++) {
        __syncthreads();   // previous GEMM done reading wsm/vsm

        // Stage weight slice [c][co] for this k2 (coalesced from g_wT)
        {
            const float4* wg   = (const float4*)(g_wT + (size_t)k2 * SMEM_WSM_F);
            float4*       wsm4 = (float4*)wsm;
#pragma unroll
            for (int i = tid; i < SMEM_WSM_F / 4; i += 256) wsm4[i] = wg[i];
        }

        // Gather v[c][p] = modulated bilinear sample
        for (int i = tid; i < C_ * PT; i += 256) {
            int c = i >> 6;          // PT == 64
            int p = i & 63;
            int s = (k2 * PT + p);
            int4   id = ((const int4*)sidx)[s];
            float4 w  = ((const float4*)swt)[s];
            const float* xc = xn + (size_t)c * HW_;
            float v = w.x * __ldg(xc + id.x)
                    + w.y * __ldg(xc + id.y)
                    + w.z * __ldg(xc + id.z)
                    + w.w * __ldg(xc + id.w);
            vsm[i] = v;              // i == c*64 + p
        }

        __syncthreads();

        // GEMM: acc[co][p] += wsm[c][co] * vsm[c][p], c = 0..127
#pragma unroll 4
        for (int c = 0; c < C_; c++) {
            float4 a0 = *(const float4*)&wsm[c * CO_ + co0];
            float4 a1 = *(const float4*)&wsm[c * CO_ + co0 + 4];
            float4 vv = *(const float4*)&vsm[c * PT + p0];
            float av[8] = {a0.x, a0.y, a0.z, a0.w, a1.x, a1.y, a1.z, a1.w};
            float bv[4] = {vv.x, vv.y, vv.z, vv.w};
#pragma unroll
            for (int i = 0; i < 8; i++)
#pragma unroll
                for (int j = 0; j < 4; j++)
                    acc[i][j] += av[i] * bv[j];
        }
    }

    // -------- Epilogue: add bias, store (float4, coalesced over p) --------
#pragma unroll
    for (int i = 0; i < 8; i++) {
        int co = co0 + i;
        float b = __ldg(bias + co);
        float4 r = make_float4(acc[i][0] + b, acc[i][1] + b,
                               acc[i][2] + b, acc[i][3] + b);
        *(float4*)&out[((size_t)(n * CO_ + co)) * HW_ + p_base + p0] = r;
    }
}

extern "C" void kernel_launch(void* const* d_in, const int* in_sizes, int n_in,
                              void* d_out, int out_size) {
    const float* x      = (const float*)d_in[0];
    const float* offset = (const float*)d_in[1];
    const float* mask   = (const float*)d_in[2];
    const float* weight = (const float*)d_in[3];
    const float* bias   = (const float*)d_in[4];
    float* out = (float*)d_out;

    cudaFuncSetAttribute(deform_conv_kernel,
                         cudaFuncAttributeMaxDynamicSharedMemorySize, SMEM_BYTES);

    transpose_weight_kernel<<<(K2_ * C_ * CO_ + 255) / 256, 256>>>(weight);
    deform_conv_kernel<<<NB * TILES_PER_IMG, 256, SMEM_BYTES>>>(x, offset, mask, bias, out);
}

// round 3
// speedup vs baseline: 8.1989x; 8.1989x over previous
#include <cuda_runtime.h>
#include <cuda_fp16.h>
#include <cstdint>

// ---------------- problem constants ----------------
#define NB   8
#define C_   128
#define H_   96
#define W_   96
#define CO_  128
#define K2_  9
#define HW_  (H_ * W_)                 // 9216
#define NPIX 128                       // output pixels per CTA tile
#define NTILES_PER_IMG (HW_ / NPIX)    // 72
#define NCHUNK (K2_ * 2)               // 18 chunks of K=64

// ---------------- smem layout (bytes) ----------------
#define SM_META_IDX  0                     // 9*128 * int4   = 18432
#define SM_META_WT   18432                 // 9*128 * float4 = 18432
#define SM_A         36864                 // 2 x 16384 (fp16 [co][c64], SW128)
#define SM_B         (SM_A + 2 * 16384)    // 69632, 2 x 16384 (fp16 [px][c64], SW128)
#define SMEM_BYTES   (SM_B + 2 * 16384)    // 102400

// ---------------- device globals (no runtime alloc) ----------------
__device__ __align__(1024) __half g_xh[(size_t)NB * HW_ * C_];       // NHWC fp16
__device__ __align__(1024) unsigned char g_wh[NCHUNK * 16384];       // pre-swizzled A tiles

// ---------------- helpers ----------------
__device__ __forceinline__ uint32_t smem_u32(const void* p) {
    uint32_t a;
    asm("{ .reg .u64 t; cvta.to.shared.u64 t, %1; cvt.u32.u64 %0, t; }" : "=r"(a) : "l"(p));
    return a;
}
#define SWZ128(o) ((o) ^ (((o) >> 3) & 0x70))

__device__ __forceinline__ void ldsm_x4(uint32_t& r0, uint32_t& r1,
                                        uint32_t& r2, uint32_t& r3, uint32_t addr) {
    asm volatile("ldmatrix.sync.aligned.m8n8.x4.shared.b16 {%0,%1,%2,%3}, [%4];"
                 : "=r"(r0), "=r"(r1), "=r"(r2), "=r"(r3) : "r"(addr));
}

__device__ __forceinline__ void hmma(float* d, const uint32_t* a, const uint32_t* b) {
    asm volatile(
        "mma.sync.aligned.m16n8k16.row.col.f32.f16.f16.f32 "
        "{%0,%1,%2,%3}, {%4,%5,%6,%7}, {%8,%9}, {%0,%1,%2,%3};"
        : "+f"(d[0]), "+f"(d[1]), "+f"(d[2]), "+f"(d[3])
        : "r"(a[0]), "r"(a[1]), "r"(a[2]), "r"(a[3]), "r"(b[0]), "r"(b[1]));
}

// ---------------- pre-kernel 1: x NCHW f32 -> NHWC f16 ----------------
__global__ void transpose_x_kernel(const float* __restrict__ x) {
    __shared__ float t[32][33];
    int n  = blockIdx.z;
    int hb = blockIdx.x * 32;
    int cb = blockIdx.y * 32;
#pragma unroll
    for (int k = 0; k < 4; k++) {
        int c = cb + threadIdx.y + k * 8;
        t[threadIdx.y + k * 8][threadIdx.x] =
            x[((size_t)n * C_ + c) * HW_ + hb + threadIdx.x];
    }
    __syncthreads();
#pragma unroll
    for (int k = 0; k < 4; k++) {
        int hw = hb + threadIdx.y + k * 8;
        g_xh[((size_t)n * HW_ + hw) * C_ + cb + threadIdx.x] =
            __float2half_rn(t[threadIdx.x][threadIdx.y + k * 8]);
    }
}

// ---------------- pre-kernel 2: weights -> pre-swizzled fp16 A tiles ----------------
// chunk (k2, half): [co=128 rows][c64=64 cols] fp16, 128B rows, SW128.
__global__ void convert_w_kernel(const float* __restrict__ w) {
    int i = blockIdx.x * 256 + threadIdx.x;
    if (i >= CO_ * C_ * K2_) return;
    int k2 = i % K2_;
    int c  = (i / K2_) % C_;
    int co = i / (K2_ * C_);
    float v = w[i];
    int h = c >> 6, c64 = c & 63;
    uint32_t off = (uint32_t)(k2 * 2 + h) * 16384u + SWZ128((uint32_t)(co * 128 + c64 * 2));
    *(__half*)(g_wh + off) = __float2half_rn(v);
}

// ---------------- main kernel ----------------
__global__ __launch_bounds__(256)
void deform_mma_kernel(const float* __restrict__ offset,
                       const float* __restrict__ mask,
                       const float* __restrict__ bias,
                       float* __restrict__ out) {
    extern __shared__ char smem[];
    uint32_t sb = smem_u32(smem);

    const int tid  = threadIdx.x;
    const int wid  = tid >> 5;
    const int lid  = tid & 31;
    const int tile = blockIdx.x;
    const int n    = tile / NTILES_PER_IMG;
    const int pbase = (tile % NTILES_PER_IMG) * NPIX;

    int4*   sidx = (int4*)(smem + SM_META_IDX);   // [9*128]
    float4* swt  = (float4*)(smem + SM_META_WT);  // [9*128]

    // --- phase 0: bilinear metadata per (k2, pixel) ---
    for (int i = tid; i < K2_ * NPIX; i += 256) {
        int k2 = i / NPIX;
        int p  = i % NPIX;
        int pg = pbase + p;
        int oy = pg / W_;
        int ox = pg % W_;

        float offY = offset[((size_t)(n * (2 * K2_) + 2 * k2)    ) * HW_ + pg];
        float offX = offset[((size_t)(n * (2 * K2_) + 2 * k2 + 1)) * HW_ + pg];
        float m    = mask  [((size_t)(n * K2_ + k2)) * HW_ + pg];

        int ky = k2 / 3, kx = k2 % 3;
        float py = (float)(oy - 1 + ky) + offY;
        float px = (float)(ox - 1 + kx) + offX;

        float y0f = floorf(py), x0f = floorf(px);
        float wy = py - y0f, wx = px - x0f;
        int y0 = (int)y0f, x0 = (int)x0f;
        int y1 = y0 + 1,   x1 = x0 + 1;

        bool vy0 = (y0 >= 0) & (y0 < H_);
        bool vy1 = (y1 >= 0) & (y1 < H_);
        bool vx0 = (x0 >= 0) & (x0 < W_);
        bool vx1 = (x1 >= 0) & (x1 < W_);

        int cy0 = min(max(y0, 0), H_ - 1);
        int cy1 = min(max(y1, 0), H_ - 1);
        int cx0 = min(max(x0, 0), W_ - 1);
        int cx1 = min(max(x1, 0), W_ - 1);

        int4 id;
        id.x = cy0 * W_ + cx0;
        id.y = cy0 * W_ + cx1;
        id.z = cy1 * W_ + cx0;
        id.w = cy1 * W_ + cx1;
        float4 wv;
        wv.x = (vy0 & vx0) ? (1.f - wy) * (1.f - wx) * m : 0.f;
        wv.y = (vy0 & vx1) ? (1.f - wy) * wx * m         : 0.f;
        wv.z = (vy1 & vx0) ? wy * (1.f - wx) * m         : 0.f;
        wv.w = (vy1 & vx1) ? wy * wx * m                 : 0.f;
        sidx[i] = id;
        swt[i]  = wv;
    }

    const __half* xh_n = g_xh + (size_t)n * HW_ * C_;

    // --- register tile: warp = 32 co x 64 px ---
    const int co0 = (wid & 3) * 32;
    const int px0 = (wid >> 2) * 64;
    const int gid = lid >> 2;
    const int tig = lid & 3;

    float acc[2][8][4];
#pragma unroll
    for (int i = 0; i < 2; i++)
#pragma unroll
        for (int j = 0; j < 8; j++)
#pragma unroll
            for (int q = 0; q < 4; q++) acc[i][j][q] = 0.f;

    // ldmatrix lane-address components
    const int lane15   = lid & 15;
    const int a_koff   = (lid >> 4) << 4;                 // +16B for k8..15 mats
    const int b_rowoff = ((lid >> 4) << 3) + (lid & 7);   // row within 16-px group
    const int b_koff   = ((lid >> 3) & 1) << 4;

    // --- main loop over 18 K-chunks (double-buffered smem) ---
    for (int ch = 0; ch < NCHUNK; ch++) {
        const int k2  = ch >> 1;
        const int hh  = ch & 1;     // channel half
        const int buf = ch & 1;

        // stage A chunk (pre-swizzled): 16KB flat copy
        {
            const uint4* ag = (const uint4*)(g_wh + (size_t)ch * 16384);
            uint4* as = (uint4*)(smem + SM_A + buf * 16384);
#pragma unroll
            for (int i = tid; i < 1024; i += 256) as[i] = ag[i];
        }

        // gather B chunk: v[p][c64] fp16, SW128
        char* bbuf = smem + SM_B + buf * 16384;
#pragma unroll
        for (int it = 0; it < 4; it++) {
            int task = it * 256 + tid;     // 0..1023
            int p = task >> 3;
            int g = task & 7;              // 8-channel group
            int s = k2 * NPIX + p;
            int4   id = sidx[s];
            float4 wv = swt[s];
            const __half* base = xh_n + hh * 64 + g * 8;

            uint4 q0 = *(const uint4*)(base + (size_t)id.x * C_);
            uint4 q1 = *(const uint4*)(base + (size_t)id.y * C_);
            uint4 q2 = *(const uint4*)(base + (size_t)id.z * C_);
            uint4 q3 = *(const uint4*)(base + (size_t)id.w * C_);

            float2 a0 = make_float2(0.f, 0.f), a1 = a0, a2 = a0, a3 = a0;
            {
                const __half2* h = (const __half2*)&q0; float2 f;
                f = __half22float2(h[0]); a0.x += wv.x * f.x; a0.y += wv.x * f.y;
                f = __half22float2(h[1]); a1.x += wv.x * f.x; a1.y += wv.x * f.y;
                f = __half22float2(h[2]); a2.x += wv.x * f.x; a2.y += wv.x * f.y;
                f = __half22float2(h[3]); a3.x += wv.x * f.x; a3.y += wv.x * f.y;
            }
            {
                const __half2* h = (const __half2*)&q1; float2 f;
                f = __half22float2(h[0]); a0.x += wv.y * f.x; a0.y += wv.y * f.y;
                f = __half22float2(h[1]); a1.x += wv.y * f.x; a1.y += wv.y * f.y;
                f = __half22float2(h[2]); a2.x += wv.y * f.x; a2.y += wv.y * f.y;
                f = __half22float2(h[3]); a3.x += wv.y * f.x; a3.y += wv.y * f.y;
            }
            {
                const __half2* h = (const __half2*)&q2; float2 f;
                f = __half22float2(h[0]); a0.x += wv.z * f.x; a0.y += wv.z * f.y;
                f = __half22float2(h[1]); a1.x += wv.z * f.x; a1.y += wv.z * f.y;
                f = __half22float2(h[2]); a2.x += wv.z * f.x; a2.y += wv.z * f.y;
                f = __half22float2(h[3]); a3.x += wv.z * f.x; a3.y += wv.z * f.y;
            }
            {
                const __half2* h = (const __half2*)&q3; float2 f;
                f = __half22float2(h[0]); a0.x += wv.w * f.x; a0.y += wv.w * f.y;
                f = __half22float2(h[1]); a1.x += wv.w * f.x; a1.y += wv.w * f.y;
                f = __half22float2(h[2]); a2.x += wv.w * f.x; a2.y += wv.w * f.y;
                f = __half22float2(h[3]); a3.x += wv.w * f.x; a3.y += wv.w * f.y;
            }
            uint4 r;
            __half2 r0 = __floats2half2_rn(a0.x, a0.y);
            __half2 r1 = __floats2half2_rn(a1.x, a1.y);
            __half2 r2 = __floats2half2_rn(a2.x, a2.y);
            __half2 r3 = __floats2half2_rn(a3.x, a3.y);
            r.x = *(uint32_t*)&r0; r.y = *(uint32_t*)&r1;
            r.z = *(uint32_t*)&r2; r.w = *(uint32_t*)&r3;
            *(uint4*)(bbuf + SWZ128((uint32_t)(p * 128 + g * 16))) = r;
        }

        __syncthreads();

        // --- HMMA on this chunk ---
        const uint32_t a_base = sb + SM_A + buf * 16384;
        const uint32_t b_base = sb + SM_B + buf * 16384;
#pragma unroll
        for (int ks = 0; ks < 4; ks++) {
            uint32_t afr[2][4];
            ldsm_x4(afr[0][0], afr[0][1], afr[0][2], afr[0][3],
                    a_base + SWZ128((uint32_t)((co0 + lane15) * 128 + ks * 32 + a_koff)));
            ldsm_x4(afr[1][0], afr[1][1], afr[1][2], afr[1][3],
                    a_base + SWZ128((uint32_t)((co0 + 16 + lane15) * 128 + ks * 32 + a_koff)));
            uint32_t bfr[8][2];
#pragma unroll
            for (int m = 0; m < 4; m++) {
                ldsm_x4(bfr[2 * m][0], bfr[2 * m][1], bfr[2 * m + 1][0], bfr[2 * m + 1][1],
                        b_base + SWZ128((uint32_t)((px0 + 16 * m + b_rowoff) * 128 + ks * 32 + b_koff)));
            }
#pragma unroll
            for (int i = 0; i < 2; i++)
#pragma unroll
                for (int j = 0; j < 8; j++)
                    hmma(acc[i][j], afr[i], bfr[j]);
        }
        // no trailing sync needed: next chunk writes the other buffer, and the
        // buffer this mma read is only rewritten after the NEXT chunk's sync.
    }

    // --- epilogue: bias + store ---
#pragma unroll
    for (int i = 0; i < 2; i++) {
        int coA = co0 + 16 * i + gid;
        float b0 = __ldg(bias + coA);
        float b1 = __ldg(bias + coA + 8);
        float* o0 = out + ((size_t)(n * CO_ + coA)) * HW_ + pbase + px0;
        float* o1 = o0 + 8 * HW_;
#pragma unroll
        for (int j = 0; j < 8; j++) {
            int px = 8 * j + 2 * tig;
            float2 v0 = make_float2(acc[i][j][0] + b0, acc[i][j][1] + b0);
            float2 v1 = make_float2(acc[i][j][2] + b1, acc[i][j][3] + b1);
            *(float2*)(o0 + px) = v0;
            *(float2*)(o1 + px) = v1;
        }
    }
}

// ---------------- launch ----------------
extern "C" void kernel_launch(void* const* d_in, const int* in_sizes, int n_in,
                              void* d_out, int out_size) {
    const float* x      = (const float*)d_in[0];
    const float* offset = (const float*)d_in[1];
    const float* mask   = (const float*)d_in[2];
    const float* weight = (const float*)d_in[3];
    const float* bias   = (const float*)d_in[4];
    float* out = (float*)d_out;

    cudaFuncSetAttribute(deform_mma_kernel,
                         cudaFuncAttributeMaxDynamicSharedMemorySize, SMEM_BYTES);

    dim3 tb(32, 8);
    dim3 tg(HW_ / 32, C_ / 32, NB);
    transpose_x_kernel<<<tg, tb>>>(x);
    convert_w_kernel<<<(CO_ * C_ * K2_ + 255) / 256, 256>>>(weight);
    deform_mma_kernel<<<NB * NTILES_PER_IMG, 256, SMEM_BYTES>>>(offset, mask, bias, out);
}

// round 4
// speedup vs baseline: 9.1522x; 1.1163x over previous
#include <cuda_runtime.h>
#include <cuda_fp16.h>
#include <cstdint>

// ---------------- problem constants ----------------
#define NB   8
#define C_   128
#define H_   96
#define W_   96
#define CO_  128
#define K2_  9
#define HW_  (H_ * W_)                 // 9216
#define NPIX 128                       // output pixels per CTA tile
#define NTILES_PER_IMG (HW_ / NPIX)    // 72
#define NCHUNK (K2_ * 2)               // 18 chunks of K=64

// ---------------- smem layout (bytes) ----------------
#define SM_META_IDX  0                     // 1152 * ushort4 = 9216
#define SM_META_WT   9216                  // 1152 * uint2   = 9216
#define SM_A         18432                 // 2 x 16384 (fp16 [co][c64], SW128) (18*1024)
#define SM_B         (SM_A + 2 * 16384)    // 51200 (50*1024), 2 x 16384
#define SMEM_BYTES   (SM_B + 2 * 16384)    // 83968

// ---------------- device globals (no runtime alloc) ----------------
__device__ __align__(1024) __half g_xh[(size_t)NB * HW_ * C_];       // NHWC fp16
__device__ __align__(1024) unsigned char g_wh[NCHUNK * 16384];       // pre-swizzled A tiles

// ---------------- helpers ----------------
__device__ __forceinline__ uint32_t smem_u32(const void* p) {
    uint32_t a;
    asm("{ .reg .u64 t; cvta.to.shared.u64 t, %1; cvt.u32.u64 %0, t; }" : "=r"(a) : "l"(p));
    return a;
}
#define SWZ128(o) ((o) ^ (((o) >> 3) & 0x70))

__device__ __forceinline__ void ldsm_x4(uint32_t& r0, uint32_t& r1,
                                        uint32_t& r2, uint32_t& r3, uint32_t addr) {
    asm volatile("ldmatrix.sync.aligned.m8n8.x4.shared.b16 {%0,%1,%2,%3}, [%4];"
                 : "=r"(r0), "=r"(r1), "=r"(r2), "=r"(r3) : "r"(addr));
}

__device__ __forceinline__ void hmma(float* d, const uint32_t* a, const uint32_t* b) {
    asm volatile(
        "mma.sync.aligned.m16n8k16.row.col.f32.f16.f16.f32 "
        "{%0,%1,%2,%3}, {%4,%5,%6,%7}, {%8,%9}, {%0,%1,%2,%3};"
        : "+f"(d[0]), "+f"(d[1]), "+f"(d[2]), "+f"(d[3])
        : "r"(a[0]), "r"(a[1]), "r"(a[2]), "r"(a[3]), "r"(b[0]), "r"(b[1]));
}

// ---------------- pre-kernel 1: x NCHW f32 -> NHWC f16 ----------------
// Block: 64 hw x 128 c tile. Grid (144, 8). float4 loads, uint4 stores.
__global__ __launch_bounds__(256)
void transpose_x_kernel(const float* __restrict__ x) {
    __shared__ __half ts[64][130];
    const int n   = blockIdx.y;
    const int hwb = blockIdx.x * 64;
    const int tid = threadIdx.x;

    // phase 1: read [c][hw] floats (float4 along hw), cvt, scatter to ts[hw][c]
#pragma unroll
    for (int i = tid; i < 128 * 16; i += 256) {
        int c   = i >> 4;
        int hw4 = (i & 15) << 2;
        float4 v = *(const float4*)(x + ((size_t)n * C_ + c) * HW_ + hwb + hw4);
        ts[hw4 + 0][c] = __float2half_rn(v.x);
        ts[hw4 + 1][c] = __float2half_rn(v.y);
        ts[hw4 + 2][c] = __float2half_rn(v.z);
        ts[hw4 + 3][c] = __float2half_rn(v.w);
    }
    __syncthreads();

    // phase 2: write NHWC rows, 8 halfs (16B) per thread, coalesced 256B/row
#pragma unroll
    for (int i = tid; i < 64 * 16; i += 256) {
        int hw = i >> 4;
        int cg = (i & 15) << 3;
        uint4 r;
        r.x = *(const uint32_t*)&ts[hw][cg + 0];
        r.y = *(const uint32_t*)&ts[hw][cg + 2];
        r.z = *(const uint32_t*)&ts[hw][cg + 4];
        r.w = *(const uint32_t*)&ts[hw][cg + 6];
        *(uint4*)(g_xh + ((size_t)n * HW_ + hwb + hw) * C_ + cg) = r;
    }
}

// ---------------- pre-kernel 2: weights -> pre-swizzled fp16 A tiles ----------------
__global__ void convert_w_kernel(const float* __restrict__ w) {
    int i = blockIdx.x * 256 + threadIdx.x;
    if (i >= CO_ * C_ * K2_) return;
    int k2 = i % K2_;
    int c  = (i / K2_) % C_;
    int co = i / (K2_ * C_);
    float v = w[i];
    int h = c >> 6, c64 = c & 63;
    uint32_t off = (uint32_t)(k2 * 2 + h) * 16384u + SWZ128((uint32_t)(co * 128 + c64 * 2));
    *(__half*)(g_wh + off) = __float2half_rn(v);
}

// ---------------- main kernel ----------------
__global__ __launch_bounds__(256, 2)
void deform_mma_kernel(const float* __restrict__ offset,
                       const float* __restrict__ mask,
                       const float* __restrict__ bias,
                       float* __restrict__ out) {
    extern __shared__ char smem[];
    uint32_t sb = smem_u32(smem);

    const int tid  = threadIdx.x;
    const int wid  = tid >> 5;
    const int lid  = tid & 31;
    const int tile = blockIdx.x;
    const int n    = tile / NTILES_PER_IMG;
    const int pbase = (tile % NTILES_PER_IMG) * NPIX;

    ushort4* sidx = (ushort4*)(smem + SM_META_IDX);   // [1152]
    uint2*   swtp = (uint2*)(smem + SM_META_WT);      // [1152] packed {w00,w01,w10,w11} fp16

    // --- phase 0: bilinear metadata per (k2, pixel) ---
    for (int i = tid; i < K2_ * NPIX; i += 256) {
        int k2 = i / NPIX;
        int p  = i % NPIX;
        int pg = pbase + p;
        int oy = pg / W_;
        int ox = pg % W_;

        float offY = offset[((size_t)(n * (2 * K2_) + 2 * k2)    ) * HW_ + pg];
        float offX = offset[((size_t)(n * (2 * K2_) + 2 * k2 + 1)) * HW_ + pg];
        float m    = mask  [((size_t)(n * K2_ + k2)) * HW_ + pg];

        int ky = k2 / 3, kx = k2 % 3;
        float py = (float)(oy - 1 + ky) + offY;
        float px = (float)(ox - 1 + kx) + offX;

        float y0f = floorf(py), x0f = floorf(px);
        float wy = py - y0f, wx = px - x0f;
        int y0 = (int)y0f, x0 = (int)x0f;
        int y1 = y0 + 1,   x1 = x0 + 1;

        bool vy0 = (y0 >= 0) & (y0 < H_);
        bool vy1 = (y1 >= 0) & (y1 < H_);
        bool vx0 = (x0 >= 0) & (x0 < W_);
        bool vx1 = (x1 >= 0) & (x1 < W_);

        int cy0 = min(max(y0, 0), H_ - 1);
        int cy1 = min(max(y1, 0), H_ - 1);
        int cx0 = min(max(x0, 0), W_ - 1);
        int cx1 = min(max(x1, 0), W_ - 1);

        ushort4 id;
        id.x = (unsigned short)(cy0 * W_ + cx0);
        id.y = (unsigned short)(cy0 * W_ + cx1);
        id.z = (unsigned short)(cy1 * W_ + cx0);
        id.w = (unsigned short)(cy1 * W_ + cx1);

        float w00 = (vy0 & vx0) ? (1.f - wy) * (1.f - wx) * m : 0.f;
        float w01 = (vy0 & vx1) ? (1.f - wy) * wx * m         : 0.f;
        float w10 = (vy1 & vx0) ? wy * (1.f - wx) * m         : 0.f;
        float w11 = (vy1 & vx1) ? wy * wx * m                 : 0.f;

        __half2 pa = __halves2half2(__float2half_rn(w00), __float2half_rn(w01));
        __half2 pb = __halves2half2(__float2half_rn(w10), __float2half_rn(w11));
        uint2 wp;
        wp.x = *(uint32_t*)&pa;
        wp.y = *(uint32_t*)&pb;
        sidx[i] = id;
        swtp[i] = wp;
    }

    const __half* xh_n = g_xh + (size_t)n * HW_ * C_;

    // --- register tile: warp = 32 co x 64 px ---
    const int co0 = (wid & 3) * 32;
    const int px0 = (wid >> 2) * 64;
    const int gid = lid >> 2;
    const int tig = lid & 3;

    float acc[2][8][4];
#pragma unroll
    for (int i = 0; i < 2; i++)
#pragma unroll
        for (int j = 0; j < 8; j++)
#pragma unroll
            for (int q = 0; q < 4; q++) acc[i][j][q] = 0.f;

    // ldmatrix lane-address components
    const int lane15   = lid & 15;
    const int a_koff   = (lid >> 4) << 4;
    const int b_rowoff = ((lid >> 4) << 3) + (lid & 7);
    const int b_koff   = ((lid >> 3) & 1) << 4;

    // --- main loop over 18 K-chunks (double-buffered smem) ---
    for (int ch = 0; ch < NCHUNK; ch++) {
        const int k2  = ch >> 1;
        const int hh  = ch & 1;     // channel half
        const int buf = ch & 1;

        // stage A chunk (pre-swizzled, L2-resident): 16KB flat copy
        {
            const uint4* ag = (const uint4*)(g_wh + (size_t)ch * 16384);
            uint4* as = (uint4*)(smem + SM_A + buf * 16384);
#pragma unroll
            for (int i = tid; i < 1024; i += 256) as[i] = ag[i];
        }

        // gather B chunk: v[p][c64] fp16, SW128; all-fp16 bilinear combine
        char* bbuf = smem + SM_B + buf * 16384;
#pragma unroll
        for (int it = 0; it < 4; it++) {
            int task = it * 256 + tid;     // 0..1023
            int p = task >> 3;
            int g = task & 7;              // 8-channel group
            int s = k2 * NPIX + p;
            ushort4 id = sidx[s];
            uint2   wp = swtp[s];

            __half2 pa = *(__half2*)&wp.x;        // {w00, w01}
            __half2 pb = *(__half2*)&wp.y;        // {w10, w11}
            __half2 w00 = __half2half2(__low2half(pa));
            __half2 w01 = __half2half2(__high2half(pa));
            __half2 w10 = __half2half2(__low2half(pb));
            __half2 w11 = __half2half2(__high2half(pb));

            const __half* base = xh_n + hh * 64 + g * 8;
            uint4 q0 = *(const uint4*)(base + ((uint32_t)id.x << 7));
            uint4 q1 = *(const uint4*)(base + ((uint32_t)id.y << 7));
            uint4 q2 = *(const uint4*)(base + ((uint32_t)id.z << 7));
            uint4 q3 = *(const uint4*)(base + ((uint32_t)id.w << 7));

            const __half2* h0 = (const __half2*)&q0;
            const __half2* h1 = (const __half2*)&q1;
            const __half2* h2 = (const __half2*)&q2;
            const __half2* h3 = (const __half2*)&q3;

            uint4 r;
            uint32_t* rp = (uint32_t*)&r;
#pragma unroll
            for (int j = 0; j < 4; j++) {
                __half2 v = __hmul2(w00, h0[j]);
                v = __hfma2(w01, h1[j], v);
                v = __hfma2(w10, h2[j], v);
                v = __hfma2(w11, h3[j], v);
                rp[j] = *(uint32_t*)&v;
            }
            *(uint4*)(bbuf + SWZ128((uint32_t)(p * 128 + g * 16))) = r;
        }

        __syncthreads();

        // --- HMMA on this chunk ---
        const uint32_t a_base = sb + SM_A + buf * 16384;
        const uint32_t b_base = sb + SM_B + buf * 16384;
#pragma unroll
        for (int ks = 0; ks < 4; ks++) {
            uint32_t afr[2][4];
            ldsm_x4(afr[0][0], afr[0][1], afr[0][2], afr[0][3],
                    a_base + SWZ128((uint32_t)((co0 + lane15) * 128 + ks * 32 + a_koff)));
            ldsm_x4(afr[1][0], afr[1][1], afr[1][2], afr[1][3],
                    a_base + SWZ128((uint32_t)((co0 + 16 + lane15) * 128 + ks * 32 + a_koff)));
            uint32_t bfr[8][2];
#pragma unroll
            for (int m = 0; m < 4; m++) {
                ldsm_x4(bfr[2 * m][0], bfr[2 * m][1], bfr[2 * m + 1][0], bfr[2 * m + 1][1],
                        b_base + SWZ128((uint32_t)((px0 + 16 * m + b_rowoff) * 128 + ks * 32 + b_koff)));
            }
#pragma unroll
            for (int i = 0; i < 2; i++)
#pragma unroll
                for (int j = 0; j < 8; j++)
                    hmma(acc[i][j], afr[i], bfr[j]);
        }
        // no trailing sync: next chunk writes the other buffer; the buffer this
        // mma read is only rewritten after the NEXT chunk's sync.
    }

    // --- epilogue: bias + store ---
#pragma unroll
    for (int i = 0; i < 2; i++) {
        int coA = co0 + 16 * i + gid;
        float b0 = __ldg(bias + coA);
        float b1 = __ldg(bias + coA + 8);
        float* o0 = out + ((size_t)(n * CO_ + coA)) * HW_ + pbase + px0;
        float* o1 = o0 + 8 * HW_;
#pragma unroll
        for (int j = 0; j < 8; j++) {
            int px = 8 * j + 2 * tig;
            float2 v0 = make_float2(acc[i][j][0] + b0, acc[i][j][1] + b0);
            float2 v1 = make_float2(acc[i][j][2] + b1, acc[i][j][3] + b1);
            *(float2*)(o0 + px) = v0;
            *(float2*)(o1 + px) = v1;
        }
    }
}

// ---------------- launch ----------------
extern "C" void kernel_launch(void* const* d_in, const int* in_sizes, int n_in,
                              void* d_out, int out_size) {
    const float* x      = (const float*)d_in[0];
    const float* offset = (const float*)d_in[1];
    const float* mask   = (const float*)d_in[2];
    const float* weight = (const float*)d_in[3];
    const float* bias   = (const float*)d_in[4];
    float* out = (float*)d_out;

    cudaFuncSetAttribute(deform_mma_kernel,
                         cudaFuncAttributeMaxDynamicSharedMemorySize, SMEM_BYTES);

    dim3 tg(HW_ / 64, NB);
    transpose_x_kernel<<<tg, 256>>>(x);
    convert_w_kernel<<<(CO_ * C_ * K2_ + 255) / 256, 256>>>(weight);
    deform_mma_kernel<<<NB * NTILES_PER_IMG, 256, SMEM_BYTES>>>(offset, mask, bias, out);
}

// round 5
// speedup vs baseline: 9.7419x; 1.0644x over previous
#include <cuda_runtime.h>
#include <cuda_fp16.h>
#include <cstdint>

// ---------------- problem constants ----------------
#define NB   8
#define C_   128
#define H_   96
#define W_   96
#define CO_  128
#define K2_  9
#define HW_  (H_ * W_)                 // 9216
#define NPIX 128                       // output pixels per CTA tile
#define NTILES_PER_IMG (HW_ / NPIX)    // 72
#define NCHUNK (K2_ * 2)               // 18 chunks of K=64

// ---------------- smem layout (bytes) ----------------
#define SM_META_IDX  0                     // 1152 * ushort4 = 9216
#define SM_META_WT   9216                  // 1152 * uint2   = 9216
#define SM_B         18432                 // 2 x 16384 (fp16 [px][c64], SW128)
#define SMEM_BYTES   (SM_B + 2 * 16384)    // 51200

// ---------------- device globals (no runtime alloc) ----------------
__device__ __align__(1024) __half g_xh[(size_t)NB * HW_ * C_];   // NHWC fp16
// A in mma-fragment order: byte addr = ch*16384 + ((tile*4 + ks)*32 + lane)*16 + reg*4 + half*2
__device__ __align__(1024) unsigned char g_wfrag[NCHUNK * 16384];

// ---------------- helpers ----------------
__device__ __forceinline__ uint32_t smem_u32(const void* p) {
    uint32_t a;
    asm("{ .reg .u64 t; cvta.to.shared.u64 t, %1; cvt.u32.u64 %0, t; }" : "=r"(a) : "l"(p));
    return a;
}
#define SWZ128(o) ((o) ^ (((o) >> 3) & 0x70))

__device__ __forceinline__ void ldsm_x4(uint32_t& r0, uint32_t& r1,
                                        uint32_t& r2, uint32_t& r3, uint32_t addr) {
    asm volatile("ldmatrix.sync.aligned.m8n8.x4.shared.b16 {%0,%1,%2,%3}, [%4];"
                 : "=r"(r0), "=r"(r1), "=r"(r2), "=r"(r3) : "r"(addr));
}

__device__ __forceinline__ void hmma(float* d, const uint32_t* a, const uint32_t* b) {
    asm volatile(
        "mma.sync.aligned.m16n8k16.row.col.f32.f16.f16.f32 "
        "{%0,%1,%2,%3}, {%4,%5,%6,%7}, {%8,%9}, {%0,%1,%2,%3};"
        : "+f"(d[0]), "+f"(d[1]), "+f"(d[2]), "+f"(d[3])
        : "r"(a[0]), "r"(a[1]), "r"(a[2]), "r"(a[3]), "r"(b[0]), "r"(b[1]));
}

// ---------------- prep kernel: x transpose + weight fragment packing ----------------
// blocks [0, 1152): x NCHW f32 -> NHWC f16 (64 hw x 128 c tile each)
// blocks [1152, 1152+36): weights -> mma-fragment-order fp16 (2048 weights each)
#define TR_BLOCKS (NB * HW_ / 64)      // 1152
#define W_BLOCKS  ((CO_ * C_ * K2_) / 2048)   // 36

__global__ __launch_bounds__(256)
void prep_kernel(const float* __restrict__ x, const float* __restrict__ w) {
    const int tid = threadIdx.x;
    if (blockIdx.x < TR_BLOCKS) {
        __shared__ __half ts[64][130];
        const int b   = blockIdx.x;
        const int n   = b / (HW_ / 64);
        const int hwb = (b % (HW_ / 64)) * 64;
#pragma unroll
        for (int i = tid; i < 128 * 16; i += 256) {
            int c   = i >> 4;
            int hw4 = (i & 15) << 2;
            float4 v = *(const float4*)(x + ((size_t)n * C_ + c) * HW_ + hwb + hw4);
            ts[hw4 + 0][c] = __float2half_rn(v.x);
            ts[hw4 + 1][c] = __float2half_rn(v.y);
            ts[hw4 + 2][c] = __float2half_rn(v.z);
            ts[hw4 + 3][c] = __float2half_rn(v.w);
        }
        __syncthreads();
#pragma unroll
        for (int i = tid; i < 64 * 16; i += 256) {
            int hw = i >> 4;
            int cg = (i & 15) << 3;
            uint4 r;
            r.x = *(const uint32_t*)&ts[hw][cg + 0];
            r.y = *(const uint32_t*)&ts[hw][cg + 2];
            r.z = *(const uint32_t*)&ts[hw][cg + 4];
            r.w = *(const uint32_t*)&ts[hw][cg + 6];
            *(uint4*)(g_xh + ((size_t)n * HW_ + hwb + hw) * C_ + cg) = r;
        }
    } else {
        // weight fragment packing
        int base = (blockIdx.x - TR_BLOCKS) * 2048;
#pragma unroll
        for (int t = 0; t < 8; t++) {
            int i = base + t * 256 + tid;          // i = (co*C + c)*9 + k2
            int k2 = i % K2_;
            int c  = (i / K2_) % C_;
            int co = i / (K2_ * C_);
            float v = w[i];
            int ch   = k2 * 2 + (c >> 6);
            int kk   = c & 63;
            int ks   = kk >> 4;
            int cl   = kk & 15;                    // k within 16-step
            int tile = co >> 4;
            int r    = co & 15;                    // row within m16 tile
            int lane = ((r & 7) << 2) | ((cl >> 1) & 3);
            int reg  = ((cl >> 3) << 1) | ((r >> 3) & 1);
            uint32_t addr = (uint32_t)ch * 16384u
                          + (uint32_t)(((tile * 4 + ks) * 32 + lane) * 16 + reg * 4 + (cl & 1) * 2);
            *(__half*)(g_wfrag + addr) = __float2half_rn(v);
        }
    }
}

// ---------------- main kernel ----------------
__global__ __launch_bounds__(256, 2)
void deform_mma_kernel(const float* __restrict__ offset,
                       const float* __restrict__ mask,
                       const float* __restrict__ bias,
                       float* __restrict__ out) {
    extern __shared__ char smem[];
    uint32_t sb = smem_u32(smem);

    const int tid  = threadIdx.x;
    const int wid  = tid >> 5;
    const int lid  = tid & 31;
    const int tile = blockIdx.x;
    const int n    = tile / NTILES_PER_IMG;
    const int pbase = (tile % NTILES_PER_IMG) * NPIX;

    ushort4* sidx = (ushort4*)(smem + SM_META_IDX);
    uint2*   swtp = (uint2*)(smem + SM_META_WT);

    // --- phase 0: bilinear metadata per (k2, pixel) ---
    for (int i = tid; i < K2_ * NPIX; i += 256) {
        int k2 = i / NPIX;
        int p  = i % NPIX;
        int pg = pbase + p;
        int oy = pg / W_;
        int ox = pg % W_;

        float offY = offset[((size_t)(n * (2 * K2_) + 2 * k2)    ) * HW_ + pg];
        float offX = offset[((size_t)(n * (2 * K2_) + 2 * k2 + 1)) * HW_ + pg];
        float m    = mask  [((size_t)(n * K2_ + k2)) * HW_ + pg];

        int ky = k2 / 3, kx = k2 % 3;
        float py = (float)(oy - 1 + ky) + offY;
        float px = (float)(ox - 1 + kx) + offX;

        float y0f = floorf(py), x0f = floorf(px);
        float wy = py - y0f, wx = px - x0f;
        int y0 = (int)y0f, x0 = (int)x0f;
        int y1 = y0 + 1,   x1 = x0 + 1;

        bool vy0 = (y0 >= 0) & (y0 < H_);
        bool vy1 = (y1 >= 0) & (y1 < H_);
        bool vx0 = (x0 >= 0) & (x0 < W_);
        bool vx1 = (x1 >= 0) & (x1 < W_);

        int cy0 = min(max(y0, 0), H_ - 1);
        int cy1 = min(max(y1, 0), H_ - 1);
        int cx0 = min(max(x0, 0), W_ - 1);
        int cx1 = min(max(x1, 0), W_ - 1);

        ushort4 id;
        id.x = (unsigned short)(cy0 * W_ + cx0);
        id.y = (unsigned short)(cy0 * W_ + cx1);
        id.z = (unsigned short)(cy1 * W_ + cx0);
        id.w = (unsigned short)(cy1 * W_ + cx1);

        float w00 = (vy0 & vx0) ? (1.f - wy) * (1.f - wx) * m : 0.f;
        float w01 = (vy0 & vx1) ? (1.f - wy) * wx * m         : 0.f;
        float w10 = (vy1 & vx0) ? wy * (1.f - wx) * m         : 0.f;
        float w11 = (vy1 & vx1) ? wy * wx * m                 : 0.f;

        __half2 pa = __halves2half2(__float2half_rn(w00), __float2half_rn(w01));
        __half2 pb = __halves2half2(__float2half_rn(w10), __float2half_rn(w11));
        uint2 wp;
        wp.x = *(uint32_t*)&pa;
        wp.y = *(uint32_t*)&pb;
        sidx[i] = id;
        swtp[i] = wp;
    }

    const __half* xh_n = g_xh + (size_t)n * HW_ * C_;

    // --- register tile: warp = 32 co x 64 px ---
    const int co0 = (wid & 3) * 32;
    const int px0 = (wid >> 2) * 64;
    const int t0  = (wid & 3) * 2;        // first m16 tile index
    const int gid = lid >> 2;
    const int tig = lid & 3;

    float acc[2][8][4];
#pragma unroll
    for (int i = 0; i < 2; i++)
#pragma unroll
        for (int j = 0; j < 8; j++)
#pragma unroll
            for (int q = 0; q < 4; q++) acc[i][j][q] = 0.f;

    const int b_rowoff = ((lid >> 4) << 3) + (lid & 7);
    const int b_koff   = ((lid >> 3) & 1) << 4;

    // --- main loop over 18 K-chunks (double-buffered B) ---
    for (int ch = 0; ch < NCHUNK; ch++) {
        const int k2  = ch >> 1;
        const int hh  = ch & 1;
        const int buf = ch & 1;

        // gather B chunk: v[p][c64] fp16, SW128; fp16 bilinear combine
        char* bbuf = smem + SM_B + buf * 16384;
#pragma unroll
        for (int it = 0; it < 4; it++) {
            int task = it * 256 + tid;     // 0..1023
            int p = task >> 3;
            int g = task & 7;
            int s = k2 * NPIX + p;
            ushort4 id = sidx[s];
            uint2   wp = swtp[s];

            __half2 pa = *(__half2*)&wp.x;
            __half2 pb = *(__half2*)&wp.y;
            __half2 w00 = __half2half2(__low2half(pa));
            __half2 w01 = __half2half2(__high2half(pa));
            __half2 w10 = __half2half2(__low2half(pb));
            __half2 w11 = __half2half2(__high2half(pb));

            const __half* base = xh_n + hh * 64 + g * 8;
            uint4 q0 = *(const uint4*)(base + ((uint32_t)id.x << 7));
            uint4 q1 = *(const uint4*)(base + ((uint32_t)id.y << 7));
            uint4 q2 = *(const uint4*)(base + ((uint32_t)id.z << 7));
            uint4 q3 = *(const uint4*)(base + ((uint32_t)id.w << 7));

            const __half2* h0 = (const __half2*)&q0;
            const __half2* h1 = (const __half2*)&q1;
            const __half2* h2 = (const __half2*)&q2;
            const __half2* h3 = (const __half2*)&q3;

            uint4 r;
            uint32_t* rp = (uint32_t*)&r;
#pragma unroll
            for (int j = 0; j < 4; j++) {
                __half2 v = __hmul2(w00, h0[j]);
                v = __hfma2(w01, h1[j], v);
                v = __hfma2(w10, h2[j], v);
                v = __hfma2(w11, h3[j], v);
                rp[j] = *(uint32_t*)&v;
            }
            *(uint4*)(bbuf + SWZ128((uint32_t)(p * 128 + g * 16))) = r;
        }

        // A fragments straight from global (fragment-order, L2-resident).
        // Issued before the barrier so L2 latency hides under sync + first LDSMs.
        uint4 af[2][4];
        {
            const uint4* abase = (const uint4*)(g_wfrag + (size_t)ch * 16384);
#pragma unroll
            for (int t = 0; t < 2; t++)
#pragma unroll
                for (int ks = 0; ks < 4; ks++)
                    af[t][ks] = __ldg(abase + ((t0 + t) * 4 + ks) * 32 + lid);
        }

        __syncthreads();

        // --- HMMA on this chunk: A from regs, B via ldmatrix ---
        const uint32_t b_base = sb + SM_B + buf * 16384;
#pragma unroll
        for (int ks = 0; ks < 4; ks++) {
            uint32_t bfr[8][2];
#pragma unroll
            for (int m = 0; m < 4; m++) {
                ldsm_x4(bfr[2 * m][0], bfr[2 * m][1], bfr[2 * m + 1][0], bfr[2 * m + 1][1],
                        b_base + SWZ128((uint32_t)((px0 + 16 * m + b_rowoff) * 128 + ks * 32 + b_koff)));
            }
#pragma unroll
            for (int i = 0; i < 2; i++)
#pragma unroll
                for (int j = 0; j < 8; j++)
                    hmma(acc[i][j], (const uint32_t*)&af[i][ks], bfr[j]);
        }
        // buffer-reuse safety: writes to this buf (chunk ch+2) happen after
        // sync(ch+1), which every warp only passes after finishing MMA(ch).
    }

    // --- epilogue: bias + store ---
#pragma unroll
    for (int i = 0; i < 2; i++) {
        int coA = co0 + 16 * i + gid;
        float b0 = __ldg(bias + coA);
        float b1 = __ldg(bias + coA + 8);
        float* o0 = out + ((size_t)(n * CO_ + coA)) * HW_ + pbase + px0;
        float* o1 = o0 + 8 * HW_;
#pragma unroll
        for (int j = 0; j < 8; j++) {
            int px = 8 * j + 2 * tig;
            float2 v0 = make_float2(acc[i][j][0] + b0, acc[i][j][1] + b0);
            float2 v1 = make_float2(acc[i][j][2] + b1, acc[i][j][3] + b1);
            *(float2*)(o0 + px) = v0;
            *(float2*)(o1 + px) = v1;
        }
    }
}

// ---------------- launch ----------------
extern "C" void kernel_launch(void* const* d_in, const int* in_sizes, int n_in,
                              void* d_out, int out_size) {
    const float* x      = (const float*)d_in[0];
    const float* offset = (const float*)d_in[1];
    const float* mask   = (const float*)d_in[2];
    const float* weight = (const float*)d_in[3];
    const float* bias   = (const float*)d_in[4];
    float* out = (float*)d_out;

    cudaFuncSetAttribute(deform_mma_kernel,
                         cudaFuncAttributeMaxDynamicSharedMemorySize, SMEM_BYTES);

    prep_kernel<<<TR_BLOCKS + W_BLOCKS, 256>>>(x, weight);
    deform_mma_kernel<<<NB * NTILES_PER_IMG, 256, SMEM_BYTES>>>(offset, mask, bias, out);
}

// round 6
// speedup vs baseline: 10.0663x; 1.0333x over previous
#include <cuda_runtime.h>
#include <cuda_fp16.h>
#include <cstdint>

// ---------------- problem constants ----------------
#define NB   8
#define C_   128
#define H_   96
#define W_   96
#define CO_  128
#define K2_  9
#define HW_  (H_ * W_)                 // 9216
#define NPIX 64                        // output pixels per CTA tile
#define NTILES_PER_IMG (HW_ / NPIX)    // 144
#define NCHUNK (K2_ * 2)               // 18 chunks of K=64

// ---------------- smem layout (bytes) ----------------
#define SM_META_IDX  0                     // 576 * ushort4 = 4608
#define SM_META_WT   4608                  // 576 * uint2   = 4608
#define SM_B         9216                  // 2 x 8192 (fp16 [px][c64], SW128)
#define SMEM_BYTES   (SM_B + 2 * 8192)     // 25600

// ---------------- device globals (no runtime alloc) ----------------
__device__ __align__(1024) __half g_xh[(size_t)NB * HW_ * C_];   // NHWC fp16
// A in mma-fragment order: byte addr = ch*16384 + ((tile*4 + ks)*32 + lane)*16 + reg*4 + half*2
__device__ __align__(1024) unsigned char g_wfrag[NCHUNK * 16384];

// ---------------- helpers ----------------
__device__ __forceinline__ uint32_t smem_u32(const void* p) {
    uint32_t a;
    asm("{ .reg .u64 t; cvta.to.shared.u64 t, %1; cvt.u32.u64 %0, t; }" : "=r"(a) : "l"(p));
    return a;
}
#define SWZ128(o) ((o) ^ (((o) >> 3) & 0x70))

__device__ __forceinline__ void ldsm_x4(uint32_t& r0, uint32_t& r1,
                                        uint32_t& r2, uint32_t& r3, uint32_t addr) {
    asm volatile("ldmatrix.sync.aligned.m8n8.x4.shared.b16 {%0,%1,%2,%3}, [%4];"
                 : "=r"(r0), "=r"(r1), "=r"(r2), "=r"(r3) : "r"(addr));
}

__device__ __forceinline__ void hmma(float* d, const uint32_t* a, const uint32_t* b) {
    asm volatile(
        "mma.sync.aligned.m16n8k16.row.col.f32.f16.f16.f32 "
        "{%0,%1,%2,%3}, {%4,%5,%6,%7}, {%8,%9}, {%0,%1,%2,%3};"
        : "+f"(d[0]), "+f"(d[1]), "+f"(d[2]), "+f"(d[3])
        : "r"(a[0]), "r"(a[1]), "r"(a[2]), "r"(a[3]), "r"(b[0]), "r"(b[1]));
}

// ---------------- prep kernel: x transpose + weight fragment packing ----------------
// blocks [0, 576): x NCHW f32 -> NHWC f16 (128 hw x 128 c tile each)
// blocks [576, 576+36): weights -> mma-fragment-order fp16 (2048 weights each)
#define TR_BLOCKS (NB * HW_ / 128)            // 576
#define W_BLOCKS  ((CO_ * C_ * K2_) / 2048)   // 36

__global__ __launch_bounds__(256)
void prep_kernel(const float* __restrict__ x, const float* __restrict__ w) {
    const int tid = threadIdx.x;
    if (blockIdx.x < TR_BLOCKS) {
        __shared__ __half ts[128][130];
        const int b   = blockIdx.x;
        const int n   = b / (HW_ / 128);
        const int hwb = (b % (HW_ / 128)) * 128;
#pragma unroll
        for (int i = tid; i < 128 * 32; i += 256) {
            int c   = i >> 5;
            int hw4 = (i & 31) << 2;
            float4 v = *(const float4*)(x + ((size_t)n * C_ + c) * HW_ + hwb + hw4);
            ts[hw4 + 0][c] = __float2half_rn(v.x);
            ts[hw4 + 1][c] = __float2half_rn(v.y);
            ts[hw4 + 2][c] = __float2half_rn(v.z);
            ts[hw4 + 3][c] = __float2half_rn(v.w);
        }
        __syncthreads();
#pragma unroll
        for (int i = tid; i < 128 * 16; i += 256) {
            int hw = i >> 4;
            int cg = (i & 15) << 3;
            uint4 r;
            r.x = *(const uint32_t*)&ts[hw][cg + 0];
            r.y = *(const uint32_t*)&ts[hw][cg + 2];
            r.z = *(const uint32_t*)&ts[hw][cg + 4];
            r.w = *(const uint32_t*)&ts[hw][cg + 6];
            *(uint4*)(g_xh + ((size_t)n * HW_ + hwb + hw) * C_ + cg) = r;
        }
    } else {
        // weight fragment packing
        int base = (blockIdx.x - TR_BLOCKS) * 2048;
#pragma unroll
        for (int t = 0; t < 8; t++) {
            int i = base + t * 256 + tid;          // i = (co*C + c)*9 + k2
            int k2 = i % K2_;
            int c  = (i / K2_) % C_;
            int co = i / (K2_ * C_);
            float v = w[i];
            int ch   = k2 * 2 + (c >> 6);
            int kk   = c & 63;
            int ks   = kk >> 4;
            int cl   = kk & 15;
            int tile = co >> 4;
            int r    = co & 15;
            int lane = ((r & 7) << 2) | ((cl >> 1) & 3);
            int reg  = ((cl >> 3) << 1) | ((r >> 3) & 1);
            uint32_t addr = (uint32_t)ch * 16384u
                          + (uint32_t)(((tile * 4 + ks) * 32 + lane) * 16 + reg * 4 + (cl & 1) * 2);
            *(__half*)(g_wfrag + addr) = __float2half_rn(v);
        }
    }
}

// ---------------- main kernel: 128 threads, 64-px tile, 4 CTAs/SM ----------------
__global__ __launch_bounds__(128, 4)
void deform_mma_kernel(const float* __restrict__ offset,
                       const float* __restrict__ mask,
                       const float* __restrict__ bias,
                       float* __restrict__ out) {
    extern __shared__ char smem[];
    uint32_t sb = smem_u32(smem);

    const int tid  = threadIdx.x;
    const int wid  = tid >> 5;
    const int lid  = tid & 31;
    const int tile = blockIdx.x;
    const int n    = tile / NTILES_PER_IMG;
    const int pbase = (tile % NTILES_PER_IMG) * NPIX;

    ushort4* sidx = (ushort4*)(smem + SM_META_IDX);
    uint2*   swtp = (uint2*)(smem + SM_META_WT);

    // --- phase 0: bilinear metadata per (k2, pixel) ---
    for (int i = tid; i < K2_ * NPIX; i += 128) {
        int k2 = i / NPIX;
        int p  = i % NPIX;
        int pg = pbase + p;
        int oy = pg / W_;
        int ox = pg % W_;

        float offY = offset[((size_t)(n * (2 * K2_) + 2 * k2)    ) * HW_ + pg];
        float offX = offset[((size_t)(n * (2 * K2_) + 2 * k2 + 1)) * HW_ + pg];
        float m    = mask  [((size_t)(n * K2_ + k2)) * HW_ + pg];

        int ky = k2 / 3, kx = k2 % 3;
        float py = (float)(oy - 1 + ky) + offY;
        float px = (float)(ox - 1 + kx) + offX;

        float y0f = floorf(py), x0f = floorf(px);
        float wy = py - y0f, wx = px - x0f;
        int y0 = (int)y0f, x0 = (int)x0f;
        int y1 = y0 + 1,   x1 = x0 + 1;

        bool vy0 = (y0 >= 0) & (y0 < H_);
        bool vy1 = (y1 >= 0) & (y1 < H_);
        bool vx0 = (x0 >= 0) & (x0 < W_);
        bool vx1 = (x1 >= 0) & (x1 < W_);

        int cy0 = min(max(y0, 0), H_ - 1);
        int cy1 = min(max(y1, 0), H_ - 1);
        int cx0 = min(max(x0, 0), W_ - 1);
        int cx1 = min(max(x1, 0), W_ - 1);

        ushort4 id;
        id.x = (unsigned short)(cy0 * W_ + cx0);
        id.y = (unsigned short)(cy0 * W_ + cx1);
        id.z = (unsigned short)(cy1 * W_ + cx0);
        id.w = (unsigned short)(cy1 * W_ + cx1);

        float w00 = (vy0 & vx0) ? (1.f - wy) * (1.f - wx) * m : 0.f;
        float w01 = (vy0 & vx1) ? (1.f - wy) * wx * m         : 0.f;
        float w10 = (vy1 & vx0) ? wy * (1.f - wx) * m         : 0.f;
        float w11 = (vy1 & vx1) ? wy * wx * m                 : 0.f;

        __half2 pa = __halves2half2(__float2half_rn(w00), __float2half_rn(w01));
        __half2 pb = __halves2half2(__float2half_rn(w10), __float2half_rn(w11));
        uint2 wp;
        wp.x = *(uint32_t*)&pa;
        wp.y = *(uint32_t*)&pb;
        sidx[i] = id;
        swtp[i] = wp;
    }

    const __half* xh_n = g_xh + (size_t)n * HW_ * C_;

    // --- register tile: warp = 32 co x 64 px ---
    const int co0 = wid * 32;
    const int t0  = wid * 2;           // first m16 tile index
    const int gid = lid >> 2;
    const int tig = lid & 3;

    float acc[2][8][4];
#pragma unroll
    for (int i = 0; i < 2; i++)
#pragma unroll
        for (int j = 0; j < 8; j++)
#pragma unroll
            for (int q = 0; q < 4; q++) acc[i][j][q] = 0.f;

    const int b_rowoff = ((lid >> 4) << 3) + (lid & 7);
    const int b_koff   = ((lid >> 3) & 1) << 4;

    // --- main loop over 18 K-chunks (double-buffered B) ---
    for (int ch = 0; ch < NCHUNK; ch++) {
        const int k2  = ch >> 1;
        const int hh  = ch & 1;
        const int buf = ch & 1;

        // A fragments from global (fragment-order, L2-resident) — issued first
        // so their latency hides under the whole gather phase.
        uint4 af[2][4];
        {
            const uint4* abase = (const uint4*)(g_wfrag + (size_t)ch * 16384);
#pragma unroll
            for (int t = 0; t < 2; t++)
#pragma unroll
                for (int ks = 0; ks < 4; ks++)
                    af[t][ks] = __ldg(abase + ((t0 + t) * 4 + ks) * 32 + lid);
        }

        // gather B chunk: v[p][c64] fp16, SW128; fp16 bilinear combine
        char* bbuf = smem + SM_B + buf * 8192;
#pragma unroll
        for (int it = 0; it < 4; it++) {
            int task = it * 128 + tid;     // 0..511
            int p = task >> 3;
            int g = task & 7;
            int s = k2 * NPIX + p;
            ushort4 id = sidx[s];
            uint2   wp = swtp[s];

            __half2 pa = *(__half2*)&wp.x;
            __half2 pb = *(__half2*)&wp.y;
            __half2 w00 = __half2half2(__low2half(pa));
            __half2 w01 = __half2half2(__high2half(pa));
            __half2 w10 = __half2half2(__low2half(pb));
            __half2 w11 = __half2half2(__high2half(pb));

            const __half* base = xh_n + hh * 64 + g * 8;
            uint4 q0 = *(const uint4*)(base + ((uint32_t)id.x << 7));
            uint4 q1 = *(const uint4*)(base + ((uint32_t)id.y << 7));
            uint4 q2 = *(const uint4*)(base + ((uint32_t)id.z << 7));
            uint4 q3 = *(const uint4*)(base + ((uint32_t)id.w << 7));

            const __half2* h0 = (const __half2*)&q0;
            const __half2* h1 = (const __half2*)&q1;
            const __half2* h2 = (const __half2*)&q2;
            const __half2* h3 = (const __half2*)&q3;

            uint4 r;
            uint32_t* rp = (uint32_t*)&r;
#pragma unroll
            for (int j = 0; j < 4; j++) {
                __half2 v = __hmul2(w00, h0[j]);
                v = __hfma2(w01, h1[j], v);
                v = __hfma2(w10, h2[j], v);
                v = __hfma2(w11, h3[j], v);
                rp[j] = *(uint32_t*)&v;
            }
            *(uint4*)(bbuf + SWZ128((uint32_t)(p * 128 + g * 16))) = r;
        }

        __syncthreads();

        // --- HMMA on this chunk: A from regs, B via ldmatrix ---
        const uint32_t b_base = sb + SM_B + buf * 8192;
#pragma unroll
        for (int ks = 0; ks < 4; ks++) {
            uint32_t bfr[8][2];
#pragma unroll
            for (int m = 0; m < 4; m++) {
                ldsm_x4(bfr[2 * m][0], bfr[2 * m][1], bfr[2 * m + 1][0], bfr[2 * m + 1][1],
                        b_base + SWZ128((uint32_t)((16 * m + b_rowoff) * 128 + ks * 32 + b_koff)));
            }
#pragma unroll
            for (int i = 0; i < 2; i++)
#pragma unroll
                for (int j = 0; j < 8; j++)
                    hmma(acc[i][j], (const uint32_t*)&af[i][ks], bfr[j]);
        }
        // buffer-reuse safety: writes to this buf (chunk ch+2) happen after
        // sync(ch+1), which every warp only passes after finishing MMA(ch).
    }

    // --- epilogue: bias + store ---
#pragma unroll
    for (int i = 0; i < 2; i++) {
        int coA = co0 + 16 * i + gid;
        float b0 = __ldg(bias + coA);
        float b1 = __ldg(bias + coA + 8);
        float* o0 = out + ((size_t)(n * CO_ + coA)) * HW_ + pbase;
        float* o1 = o0 + 8 * HW_;
#pragma unroll
        for (int j = 0; j < 8; j++) {
            int px = 8 * j + 2 * tig;
            float2 v0 = make_float2(acc[i][j][0] + b0, acc[i][j][1] + b0);
            float2 v1 = make_float2(acc[i][j][2] + b1, acc[i][j][3] + b1);
            *(float2*)(o0 + px) = v0;
            *(float2*)(o1 + px) = v1;
        }
    }
}

// ---------------- launch ----------------
extern "C" void kernel_launch(void* const* d_in, const int* in_sizes, int n_in,
                              void* d_out, int out_size) {
    const float* x      = (const float*)d_in[0];
    const float* offset = (const float*)d_in[1];
    const float* mask   = (const float*)d_in[2];
    const float* weight = (const float*)d_in[3];
    const float* bias   = (const float*)d_in[4];
    float* out = (float*)d_out;

    cudaFuncSetAttribute(deform_mma_kernel,
                         cudaFuncAttributeMaxDynamicSharedMemorySize, SMEM_BYTES);

    prep_kernel<<<TR_BLOCKS + W_BLOCKS, 256>>>(x, weight);
    deform_mma_kernel<<<NB * NTILES_PER_IMG, 128, SMEM_BYTES>>>(offset, mask, bias, out);
}